// round 1
// baseline (speedup 1.0000x reference)
#include <cuda_runtime.h>
#include <cstdint>

// ---------------------------------------------------------------------------
// Problem constants
// ---------------------------------------------------------------------------
#define BB 64
#define CC 3
#define HH 384
#define WW 384
#define HW (HH * WW)            // 147456
#define CHW (CC * HW)           // 442368
#define NTOT (BB * CHW)         // 28311552
#define N4 (NTOT / 4)           // 7077888

// ---------------------------------------------------------------------------
// constexpr threefry2x32 (JAX rotation schedule) — used at COMPILE TIME to
// derive the 6 child keys of jax.random.split(jax.random.key(42), 6) under
// the partitionable (fold-like) scheme: child i = threefry(master, 0, i).
// ---------------------------------------------------------------------------
constexpr unsigned long long tf_pair_ce(unsigned k0, unsigned k1,
                                        unsigned x0, unsigned x1) {
    unsigned k2 = k0 ^ k1 ^ 0x1BD11BDAu;
    x0 += k0; x1 += k1;
    const int rots[5][4] = {{13,15,26,6},{17,29,16,24},{13,15,26,6},
                            {17,29,16,24},{13,15,26,6}};
    const unsigned ka[5] = {k1, k2, k0, k1, k2};
    const unsigned kb[5] = {k2, k0, k1, k2, k0};
    for (int g = 0; g < 5; ++g) {
        for (int j = 0; j < 4; ++j) {
            x0 += x1;
            int r = rots[g][j];
            x1 = (x1 << r) | (x1 >> (32 - r));
            x1 ^= x0;
        }
        x0 += ka[g];
        x1 += kb[g] + (unsigned)(g + 1);
    }
    return ((unsigned long long)x0 << 32) | (unsigned long long)x1;
}

// master key for jax.random.key(42) is (0, 42)
constexpr unsigned long long KP_ = tf_pair_ce(0u, 42u, 0u, 0u);
constexpr unsigned long long KA_ = tf_pair_ce(0u, 42u, 0u, 1u);
constexpr unsigned long long KR_ = tf_pair_ce(0u, 42u, 0u, 2u);
constexpr unsigned long long KT_ = tf_pair_ce(0u, 42u, 0u, 3u);
constexpr unsigned long long KL_ = tf_pair_ce(0u, 42u, 0u, 4u);
constexpr unsigned long long KN_ = tf_pair_ce(0u, 42u, 0u, 5u);

#define KHI(k) ((unsigned)((k) >> 32))
#define KLO(k) ((unsigned)((k) & 0xFFFFFFFFull))

// ---------------------------------------------------------------------------
// Device threefry: random_bits (partitionable) for 32-bit width and counts
// < 2^32:  bits(i) = out0 ^ out1 of threefry(key, x0=0, x1=i).
// ---------------------------------------------------------------------------
__device__ __forceinline__ unsigned tf_bits(unsigned k0, unsigned k1, unsigned ctr) {
    unsigned k2 = k0 ^ k1 ^ 0x1BD11BDAu;
    unsigned x0 = k0;          // 0 + k0
    unsigned x1 = ctr + k1;
#define TFR(r) { x0 += x1; x1 = __funnelshift_l(x1, x1, (r)); x1 ^= x0; }
    TFR(13) TFR(15) TFR(26) TFR(6)
    x0 += k1; x1 += k2 + 1u;
    TFR(17) TFR(29) TFR(16) TFR(24)
    x0 += k2; x1 += k0 + 2u;
    TFR(13) TFR(15) TFR(26) TFR(6)
    x0 += k0; x1 += k1 + 3u;
    TFR(17) TFR(29) TFR(16) TFR(24)
    x0 += k1; x1 += k2 + 4u;
    TFR(13) TFR(15) TFR(26) TFR(6)
    x0 += k2; x1 += k0 + 5u;
#undef TFR
    return x0 ^ x1;
}

// bits -> float in [0, 1): bitcast((bits>>9)|0x3f800000) - 1.0  (JAX _uniform)
__device__ __forceinline__ float u01(unsigned bits) {
    return __uint_as_float((bits >> 9) | 0x3F800000u) - 1.0f;
}

// ---------------------------------------------------------------------------
// Per-sample erase rectangle: {top, bottom, left, right}; empty if not applied
// ---------------------------------------------------------------------------
__device__ int4 g_rect[BB];

__global__ void setup_kernel() {
    int b = threadIdx.x;
    if (b >= BB) return;

    // apply = uniform(kp) <= 0.5
    float up = u01(tf_bits(KHI(KP_), KLO(KP_), (unsigned)b));
    bool apply = (up <= 0.5f);

    // target area: uniform in [0.02, 0.33] * (H*W)
    float ua = u01(tf_bits(KHI(KA_), KLO(KA_), (unsigned)b));
    const float RA = 0.33f - 0.02f;               // f32 exact as XLA computes it
    float ta_u = fmaxf(0.02f, __fadd_rn(__fmul_rn(ua, RA), 0.02f));
    float ta = __fmul_rn(ta_u, 147456.0f);

    // aspect ratio: uniform in [0.3, 3.3]
    float ur = u01(tf_bits(KHI(KR_), KLO(KR_), (unsigned)b));
    const float RR = 3.3f - 0.3f;
    float ar = fmaxf(0.3f, __fadd_rn(__fmul_rn(ur, RR), 0.3f));

    // h_e = round(sqrt(ta*ar)); w_e = round(sqrt(ta/ar))  (round half to even)
    int h_e = (int)rintf(__fsqrt_rn(__fmul_rn(ta, ar)));
    int w_e = (int)rintf(__fsqrt_rn(__fdiv_rn(ta, ar)));

    bool valid = apply && (h_e < HH) && (w_e < WW);

    // top = floor(u * (H - h_e + 1)); left = floor(u * (W - w_e + 1))
    float ut = u01(tf_bits(KHI(KT_), KLO(KT_), (unsigned)b));
    float ul = u01(tf_bits(KHI(KL_), KLO(KL_), (unsigned)b));
    int top  = (int)floorf(__fmul_rn(ut, (float)(HH - h_e + 1)));
    int left = (int)floorf(__fmul_rn(ul, (float)(WW - w_e + 1)));

    int4 r;
    if (valid) { r.x = top; r.y = top + h_e; r.z = left; r.w = left + w_e; }
    else       { r.x = 0;   r.y = 0;         r.z = 0;    r.w = 0; }
    g_rect[b] = r;
}

// ---------------------------------------------------------------------------
// Noise for global element index i (JAX normal: sqrt(2)*erfinv(uniform(-1,1)))
// ---------------------------------------------------------------------------
__device__ __forceinline__ float noise_at(unsigned i) {
    unsigned bits = tf_bits(KHI(KN_), KLO(KN_), i);
    float u = u01(bits);
    const float LO = -0.99999994039535522461f;    // nextafter(-1, 0) in f32
    // hi - lo rounds to exactly 2.0f in f32
    float v = fmaxf(LO, __fadd_rn(__fmul_rn(u, 2.0f), LO));
    return __uint_as_float(0x3FB504F3u) * erfinvf(v);   // f32(sqrt(2)) * erfinv
}

// ---------------------------------------------------------------------------
// Main streaming kernel: one float4 (4 consecutive w) per thread
// ---------------------------------------------------------------------------
__global__ void __launch_bounds__(256)
erase_kernel(const float4* __restrict__ x,
             const float* __restrict__ mean,
             const float* __restrict__ stdv,
             float4* __restrict__ out) {
    int t = blockIdx.x * blockDim.x + threadIdx.x;
    if (t >= N4) return;

    int i = t * 4;                     // global element index of lane 0
    int b  = i / CHW;
    int r0 = i - b * CHW;
    int c  = r0 / HW;
    int r1 = r0 - c * HW;
    int h  = r1 / WW;
    int w  = r1 - h * WW;              // multiple of 4

    float4 v = x[t];
    float m   = __ldg(&mean[c]);
    float inv = 1.0f / __ldg(&stdv[c]);

    float4 o;
    o.x = (v.x - m) * inv;
    o.y = (v.y - m) * inv;
    o.z = (v.z - m) * inv;
    o.w = (v.w - m) * inv;

    int4 rc = g_rect[b];
    if (h >= rc.x && h < rc.y) {
        // column range [rc.z, rc.w)
        if (w + 0 >= rc.z && w + 0 < rc.w) o.x = noise_at((unsigned)(i + 0));
        if (w + 1 >= rc.z && w + 1 < rc.w) o.y = noise_at((unsigned)(i + 1));
        if (w + 2 >= rc.z && w + 2 < rc.w) o.z = noise_at((unsigned)(i + 2));
        if (w + 3 >= rc.z && w + 3 < rc.w) o.w = noise_at((unsigned)(i + 3));
    }

    out[t] = o;
}

// ---------------------------------------------------------------------------
// Launch
// ---------------------------------------------------------------------------
extern "C" void kernel_launch(void* const* d_in, const int* in_sizes, int n_in,
                              void* d_out, int out_size) {
    const float4* x   = (const float4*)d_in[0];
    const float*  mn  = (const float*)d_in[1];
    const float*  sd  = (const float*)d_in[2];
    float4*       out = (float4*)d_out;

    setup_kernel<<<1, 64>>>();
    erase_kernel<<<(N4 + 255) / 256, 256>>>(x, mn, sd, out);
}

// round 7
// speedup vs baseline: 1.1379x; 1.1379x over previous
#include <cuda_runtime.h>
#include <cstdint>

// ---------------------------------------------------------------------------
// Problem constants
// ---------------------------------------------------------------------------
#define BB 64
#define CC 3
#define HH 384
#define WW 384
#define HW (HH * WW)            // 147456
#define CHW (CC * HW)           // 442368
#define NTOT (BB * CHW)         // 28311552
// 16 floats (64B) per thread; W % 16 == 0 so a chunk never straddles a row
#define CPR  (WW / 16)          // chunks per row         = 24
#define CPC  (HW / 16)          // chunks per channel     = 9216
#define CPI  (CHW / 16)         // chunks per image       = 27648
#define NCH  (NTOT / 16)        // total chunks           = 1769472

// ---------------------------------------------------------------------------
// constexpr threefry2x32 (JAX schedule) — compile-time child keys of
// jax.random.split(jax.random.key(42), 6), partitionable: child i = tf(k,0,i)
// ---------------------------------------------------------------------------
constexpr unsigned long long tf_pair_ce(unsigned k0, unsigned k1,
                                        unsigned x0, unsigned x1) {
    unsigned k2 = k0 ^ k1 ^ 0x1BD11BDAu;
    x0 += k0; x1 += k1;
    const int rots[5][4] = {{13,15,26,6},{17,29,16,24},{13,15,26,6},
                            {17,29,16,24},{13,15,26,6}};
    const unsigned ka[5] = {k1, k2, k0, k1, k2};
    const unsigned kb[5] = {k2, k0, k1, k2, k0};
    for (int g = 0; g < 5; ++g) {
        for (int j = 0; j < 4; ++j) {
            x0 += x1;
            int r = rots[g][j];
            x1 = (x1 << r) | (x1 >> (32 - r));
            x1 ^= x0;
        }
        x0 += ka[g];
        x1 += kb[g] + (unsigned)(g + 1);
    }
    return ((unsigned long long)x0 << 32) | (unsigned long long)x1;
}

constexpr unsigned long long KP_ = tf_pair_ce(0u, 42u, 0u, 0u);
constexpr unsigned long long KA_ = tf_pair_ce(0u, 42u, 0u, 1u);
constexpr unsigned long long KR_ = tf_pair_ce(0u, 42u, 0u, 2u);
constexpr unsigned long long KT_ = tf_pair_ce(0u, 42u, 0u, 3u);
constexpr unsigned long long KL_ = tf_pair_ce(0u, 42u, 0u, 4u);
constexpr unsigned long long KN_ = tf_pair_ce(0u, 42u, 0u, 5u);

#define KHI(k) ((unsigned)((k) >> 32))
#define KLO(k) ((unsigned)((k) & 0xFFFFFFFFull))

// ---------------------------------------------------------------------------
// Device threefry: bits(i) = out0 ^ out1 of threefry(key, 0, i)
// ---------------------------------------------------------------------------
__device__ __forceinline__ unsigned tf_bits(unsigned k0, unsigned k1, unsigned ctr) {
    unsigned k2 = k0 ^ k1 ^ 0x1BD11BDAu;
    unsigned x0 = k0;
    unsigned x1 = ctr + k1;
#define TFR(r) { x0 += x1; x1 = __funnelshift_l(x1, x1, (r)); x1 ^= x0; }
    TFR(13) TFR(15) TFR(26) TFR(6)
    x0 += k1; x1 += k2 + 1u;
    TFR(17) TFR(29) TFR(16) TFR(24)
    x0 += k2; x1 += k0 + 2u;
    TFR(13) TFR(15) TFR(26) TFR(6)
    x0 += k0; x1 += k1 + 3u;
    TFR(17) TFR(29) TFR(16) TFR(24)
    x0 += k1; x1 += k2 + 4u;
    TFR(13) TFR(15) TFR(26) TFR(6)
    x0 += k2; x1 += k0 + 5u;
#undef TFR
    return x0 ^ x1;
}

__device__ __forceinline__ float u01(unsigned bits) {
    return __uint_as_float((bits >> 9) | 0x3F800000u) - 1.0f;
}

// ---------------------------------------------------------------------------
// Per-sample erase rectangle {top, bottom, left, right}; empty when invalid
// ---------------------------------------------------------------------------
__device__ int4 g_rect[BB];

__global__ void setup_kernel() {
    int b = threadIdx.x;
    if (b >= BB) return;

    float up = u01(tf_bits(KHI(KP_), KLO(KP_), (unsigned)b));
    bool apply = (up <= 0.5f);

    float ua = u01(tf_bits(KHI(KA_), KLO(KA_), (unsigned)b));
    const float RA = 0.33f - 0.02f;
    float ta_u = fmaxf(0.02f, __fadd_rn(__fmul_rn(ua, RA), 0.02f));
    float ta = __fmul_rn(ta_u, 147456.0f);

    float ur = u01(tf_bits(KHI(KR_), KLO(KR_), (unsigned)b));
    const float RR = 3.3f - 0.3f;
    float ar = fmaxf(0.3f, __fadd_rn(__fmul_rn(ur, RR), 0.3f));

    int h_e = (int)rintf(__fsqrt_rn(__fmul_rn(ta, ar)));
    int w_e = (int)rintf(__fsqrt_rn(__fdiv_rn(ta, ar)));

    bool valid = apply && (h_e < HH) && (w_e < WW);

    float ut = u01(tf_bits(KHI(KT_), KLO(KT_), (unsigned)b));
    float ul = u01(tf_bits(KHI(KL_), KLO(KL_), (unsigned)b));
    int top  = (int)floorf(__fmul_rn(ut, (float)(HH - h_e + 1)));
    int left = (int)floorf(__fmul_rn(ul, (float)(WW - w_e + 1)));

    int4 r;
    if (valid) { r.x = top; r.y = top + h_e; r.z = left; r.w = left + w_e; }
    else       { r.x = 0;   r.y = 0;         r.z = 0;    r.w = 0; }
    g_rect[b] = r;
}

// ---------------------------------------------------------------------------
// Noise at global element index i (JAX normal = sqrt(2)*erfinv(uniform(-1,1)))
// ---------------------------------------------------------------------------
__device__ __forceinline__ float noise_at(unsigned i) {
    unsigned bits = tf_bits(KHI(KN_), KLO(KN_), i);
    float u = u01(bits);
    const float LO = -0.99999994039535522461f;    // nextafter(-1,0) f32
    float v = fmaxf(LO, __fadd_rn(__fmul_rn(u, 2.0f), LO));
    return __uint_as_float(0x3FB504F3u) * erfinvf(v);
}

// ---------------------------------------------------------------------------
// Main streaming kernel: 16 contiguous floats (4x float4) per thread.
// A 16-float aligned chunk lies entirely within one (b, c, h) row.
// All data lives in ONE aligned float[16] array so the (fully unrolled,
// constant-index) erase loop legally writes the same storage the final
// vector stores read — everything stays in registers.
// ---------------------------------------------------------------------------
__global__ void __launch_bounds__(256)
erase_kernel(const float4* __restrict__ x,
             const float* __restrict__ mean,
             const float* __restrict__ stdv,
             float4* __restrict__ out) {
    int t = blockIdx.x * blockDim.x + threadIdx.x;   // chunk id, < NCH
    if (t >= NCH) return;

    // decode chunk -> (b, c, h, w0) once
    int b  = t / CPI;
    int r0 = t - b * CPI;
    int c  = r0 / CPC;
    int r1 = r0 - c * CPC;
    int h  = r1 / CPR;
    int w0 = (r1 - h * CPR) << 4;        // starting w of this 16-float chunk

    // batch the 4 vector loads for MLP=4
    alignas(16) float o[16];
    float4* ov4 = reinterpret_cast<float4*>(o);
    const float4* xp = x + (size_t)t * 4;
    ov4[0] = xp[0];
    ov4[1] = xp[1];
    ov4[2] = xp[2];
    ov4[3] = xp[3];

    float inv  = 1.0f / __ldg(&stdv[c]);
    float bias = -__ldg(&mean[c]) * inv;

    #pragma unroll
    for (int j = 0; j < 16; ++j)
        o[j] = fmaf(o[j], inv, bias);

    int4 rc = g_rect[b];
    // row-range + column-overlap test once per thread; rare path per-lane
    if (h >= rc.x && h < rc.y && w0 + 15 >= rc.z && w0 < rc.w) {
        unsigned i0 = (unsigned)t * 16u;   // global element index of lane 0
        #pragma unroll
        for (int j = 0; j < 16; ++j) {
            int w = w0 + j;
            if (w >= rc.z && w < rc.w) o[j] = noise_at(i0 + (unsigned)j);
        }
    }

    float4* op = out + (size_t)t * 4;
    op[0] = ov4[0];
    op[1] = ov4[1];
    op[2] = ov4[2];
    op[3] = ov4[3];
}

// ---------------------------------------------------------------------------
// Launch
// ---------------------------------------------------------------------------
extern "C" void kernel_launch(void* const* d_in, const int* in_sizes, int n_in,
                              void* d_out, int out_size) {
    const float4* x   = (const float4*)d_in[0];
    const float*  mn  = (const float*)d_in[1];
    const float*  sd  = (const float*)d_in[2];
    float4*       out = (float4*)d_out;

    setup_kernel<<<1, 64>>>();
    erase_kernel<<<(NCH + 255) / 256, 256>>>(x, mn, sd, out);
}